// round 2
// baseline (speedup 1.0000x reference)
#include <cuda_runtime.h>

#define INPN 1024
#define NN   8000
#define NEE  6400
#define NII  1600
#define TS   1000
#define PRB0 200
#define NWE  200   /* NEE/32 */
#define NWI  50    /* NII/32 */
#define DECAYF 0.95f
#define VTHF   0.5f

#define SIM_NB 25
#define SIM_NT 320
#define WPC    10   /* warps per CTA in k_sim */

// ---------------- device scratch (static: no allocation APIs) ----------------
__device__ float    d_D[(size_t)TS * NN];      // per-step input drive [t][j], 32 MB
__device__ unsigned d_bitsT[INPN * 32];        // input spike bits: [i][word], bit k = sp(t=32w+k, i)
__device__ float    d_csEae[NEE];              // colsum of E-rows of w_ae
__device__ float    d_csIae[NEE];              // colsum of I-rows of w_ae
__device__ float    d_csEai[NII];              // colsum of E-rows of w_ai
__device__ float    d_csIai[NII];              // colsum of I-rows of w_ai
__device__ unsigned d_mE[3][NWE];              // E spike masks, ring of 3 steps
__device__ unsigned d_mI[3][NWI];              // I spike masks
__device__ int      d_cE[TS];                  // E spike counts per step
__device__ int      d_cI[TS];                  // I spike counts per step
__device__ volatile unsigned d_barcnt;         // monotonic grid barrier counter

// ---------------- K0: reset scratch ----------------
__global__ void k_reset() {
  int tid = blockIdx.x * blockDim.x + threadIdx.x;
  int total = TS * 2 + NEE * 2 + NII * 2;
  for (int i = tid; i < total; i += gridDim.x * blockDim.x) {
    int x = i;
    if (x < TS) { d_cE[x] = 0; continue; } x -= TS;
    if (x < TS) { d_cI[x] = 0; continue; } x -= TS;
    if (x < NEE) { d_csEae[x] = 0.f; continue; } x -= NEE;
    if (x < NEE) { d_csIae[x] = 0.f; continue; } x -= NEE;
    if (x < NII) { d_csEai[x] = 0.f; continue; } x -= NII;
    d_csIai[x] = 0.f;
  }
  if (tid == 0) d_barcnt = 0u;
}

// ---------------- K1: pack input spike bits (transposed) ----------------
__global__ void k_bits(const float* __restrict__ inp, const float* __restrict__ rand_p) {
  int i = blockIdx.x * blockDim.x + threadIdx.x;
  if (i >= INPN) return;
  float th = inp[i] * 0.5f;   // RATE = 0.5
  for (int w = 0; w < 32; ++w) {
    unsigned m = 0u;
    int t0 = w * 32;
#pragma unroll
    for (int k = 0; k < 32; ++k) {
      int t = t0 + k;
      if (t < TS && rand_p[(size_t)t * INPN + i] <= th) m |= (1u << k);
    }
    d_bitsT[i * 32 + w] = m;
  }
}

// ---------------- K2: column sums of E-row and I-row blocks ----------------
// which = 0 -> w_ae targets (d_csEae/d_csIae), which = 1 -> w_ai targets.
// NOTE: destination arrays are selected in DEVICE code (a __device__ symbol
// must never be passed as a kernel argument from host code).
__global__ void k_colsum(const float* __restrict__ W, int ncols, int which) {
  int j = blockIdx.x * blockDim.x + threadIdx.x;
  if (j >= ncols) return;
  int c = blockIdx.y;   // 0..19 : 16 chunks of 400 E rows, 4 chunks of 400 I rows
  int base = (c < 16) ? (INPN + c * 400) : (INPN + NEE + (c - 16) * 400);
  const float* p = W + (size_t)base * ncols + j;
  float s = 0.f;
#pragma unroll 4
  for (int r = 0; r < 400; ++r) s += p[(size_t)r * ncols];
  float* dst;
  if (c < 16) dst = which ? d_csEai : d_csEae;
  else        dst = which ? d_csIai : d_csIae;
  atomicAdd(&dst[j], s);
}

// ---------------- K3: input drive D[t][j] = sum_i sp(t,i) * W_in[i][j] ----------------
__global__ void __launch_bounds__(256) k_indrive(const float* __restrict__ w_ae,
                                                 const float* __restrict__ w_ai) {
  int j = blockIdx.x * 256 + threadIdx.x;
  if (j >= NN) return;
  int wt = blockIdx.y;                 // t-word: covers t in [32*wt, 32*wt+32)
  const float* col;
  int stride;
  if (j < NEE) { col = w_ae + j;          stride = NEE; }
  else         { col = w_ai + (j - NEE);  stride = NII; }
  float acc[32];
#pragma unroll
  for (int k = 0; k < 32; ++k) acc[k] = 0.f;
#pragma unroll 4
  for (int i = 0; i < INPN; ++i) {
    float w = __ldg(col + (size_t)i * stride);
    unsigned m = d_bitsT[i * 32 + wt];
#pragma unroll
    for (int k = 0; k < 32; ++k)
      if (m & (1u << k)) acc[k] += w;
  }
  int t0 = wt * 32;
#pragma unroll
  for (int k = 0; k < 32; ++k) {
    int t = t0 + k;
    if (t < TS) d_D[(size_t)t * NN + j] = acc[k];
  }
}

// ---------------- K4: persistent recurrent simulation ----------------
// contribution of one row-group (active-gather vs colsum-minus-inactive)
__device__ __forceinline__ float gather_group(const float* __restrict__ base, int stride,
                                              const unsigned* __restrict__ mask,
                                              int cnt, int gsize, int nw, float colsum) {
  if (cnt == 0)     return 0.f;
  if (cnt == gsize) return colsum;                 // exact: full activity -> column sum
  bool comp = (2 * cnt > gsize);
  float acc = comp ? colsum : 0.f;
  float sgn = comp ? -1.f : 1.f;
  for (int wd = 0; wd < nw; ++wd) {
    unsigned x = __ldcg(&mask[wd]);
    if (comp) x = ~x;
    while (x) {                                    // warp-uniform: deterministic order
      int b = __ffs(x) - 1;
      x &= x - 1;
      acc = fmaf(sgn, __ldg(base + (size_t)(wd * 32 + b) * stride), acc);
    }
  }
  return acc;
}

__global__ void __launch_bounds__(SIM_NT, 1) k_sim(const float* __restrict__ w_ae,
                                                   const float* __restrict__ w_ai,
                                                   float* __restrict__ out) {
  __shared__ int s_pc[WPC];
  const int tid = blockIdx.x * SIM_NT + threadIdx.x;   // 25*320 = 8000: all active
  const bool isE = (tid < NEE);                        // uniform per CTA (boundary at CTA 20)
  const int col = isE ? tid : tid - NEE;
  const int stride = isE ? NEE : NII;
  const float* W = isE ? w_ae : w_ai;
  const float* baseE = W + (size_t)INPN * stride + col;           // E-row block
  const float* baseI = W + (size_t)(INPN + NEE) * stride + col;   // I-row block
  const float csE = isE ? d_csEae[col] : d_csEai[col];
  const float csI = isE ? d_csIae[col] : d_csIai[col];
  float v = 0.f, ssum = 0.f;
  const unsigned nb = gridDim.x;

  for (int t = 0; t < TS; ++t) {
    float a = __ldg(&d_D[(size_t)t * NN + tid]);
    // E targets: E rows @ t-2 (slp), I rows @ t-1 (sl)
    // I targets: E rows @ t-1 (sl),  I rows @ t-2 (slp)
    int ageE = t - (isE ? 2 : 1);
    int ageI = t - (isE ? 1 : 2);
    if (ageE >= 0) {
      int c = __ldcg(&d_cE[ageE]);
      a += gather_group(baseE, stride, d_mE[ageE % 3], c, NEE, NWE, csE);
    }
    if (ageI >= 0) {
      int c = __ldcg(&d_cI[ageI]);
      a += gather_group(baseI, stride, d_mI[ageI % 3], c, NII, NWI, csI);
    }
    v = v * DECAYF + a;
    bool sp = (v >= VTHF);
    if (sp) v = 0.f;
    if (sp && isE && t >= PRB0) ssum += 1.f;

    // publish spikes for step t (each warp is purely E or purely I)
    unsigned bal = __ballot_sync(0xffffffffu, sp);
    if ((threadIdx.x & 31) == 0) {
      int gw = tid >> 5;
      int s = t % 3;
      if (isE) d_mE[s][gw] = bal;
      else     d_mI[s][gw - NWE] = bal;
      s_pc[threadIdx.x >> 5] = __popc(bal);
    }
    // ---- per-CTA count aggregation + grid barrier (monotonic counter) ----
    __syncthreads();
    if (threadIdx.x == 0) {
      int tot = 0;
#pragma unroll
      for (int w = 0; w < WPC; ++w) tot += s_pc[w];
      if (isE) atomicAdd(&d_cE[t], tot);
      else     atomicAdd(&d_cI[t], tot);
      __threadfence();
      atomicAdd((unsigned*)&d_barcnt, 1u);
      unsigned want = (unsigned)(t + 1) * nb;
      while (d_barcnt < want) { }
      __threadfence();
    }
    __syncthreads();
  }
  if (isE) out[col] = ssum * (1.0f / 800.0f);
}

// ---------------- launcher ----------------
extern "C" void kernel_launch(void* const* d_in, const int* in_sizes, int n_in,
                              void* d_out, int out_size) {
  // bind inputs by element count (all four are distinct sizes)
  const float *inp = 0, *w_ae = 0, *w_ai = 0, *rand_p = 0;
  for (int i = 0; i < n_in; ++i) {
    switch (in_sizes[i]) {
      case 1024:      inp    = (const float*)d_in[i]; break;
      case 57753600:  w_ae   = (const float*)d_in[i]; break;   // 9024*6400
      case 14438400:  w_ai   = (const float*)d_in[i]; break;   // 9024*1600
      case 1024000:   rand_p = (const float*)d_in[i]; break;   // 1000*1024
    }
  }
  float* out = (float*)d_out;

  k_reset<<<32, 256>>>();
  k_bits<<<8, 128>>>(inp, rand_p);
  {
    dim3 g((NEE + 255) / 256, 20);
    k_colsum<<<g, 256>>>(w_ae, NEE, 0);
  }
  {
    dim3 g((NII + 255) / 256, 20);
    k_colsum<<<g, 256>>>(w_ai, NII, 1);
  }
  {
    dim3 g((NN + 255) / 256, 32);
    k_indrive<<<g, 256>>>(w_ae, w_ai);
  }
  k_sim<<<SIM_NB, SIM_NT>>>(w_ae, w_ai, out);
}

// round 3
// speedup vs baseline: 1.1869x; 1.1869x over previous
#include <cuda_runtime.h>
#include <cuda_bf16.h>
#include <mma.h>

using namespace nvcuda;

#define INPN 1024
#define NN   8000
#define NEE  6400
#define NII  1600
#define TS   1000
#define TSP  1024   /* padded t rows for GEMM */
#define PRB0 200
#define NWE  200    /* NEE/32 */
#define NWI  50     /* NII/32 */
#define DECAYF 0.95f
#define VTHF   0.5f

#define SIM_NB 25
#define SIM_NT 320
#define WPC    10   /* warps per CTA in k_sim */

// ---------------- device scratch (static: no allocation APIs) ----------------
__device__ float         d_Dp[(size_t)TSP * NN];     // input drive, padded [1024][8000]
__device__ __nv_bfloat16 d_S[(size_t)TSP * INPN];    // spike matrix S[t][i] in {0,1}, rows >=1000 zero
__device__ __nv_bfloat16 d_Whi[(size_t)INPN * NN];   // hi bf16 split of W_in[k][j]
__device__ __nv_bfloat16 d_Wlo[(size_t)INPN * NN];   // lo bf16 split
__device__ float    d_csEae[NEE];
__device__ float    d_csIae[NEE];
__device__ float    d_csEai[NII];
__device__ float    d_csIai[NII];
__device__ unsigned d_mE[3][NWE];
__device__ unsigned d_mI[3][NWI];
__device__ int      d_cE[TS];
__device__ int      d_cI[TS];
__device__ volatile unsigned d_barcnt;

// ---------------- K0: reset scratch ----------------
__global__ void k_reset() {
  int tid = blockIdx.x * blockDim.x + threadIdx.x;
  int total = TS * 2 + NEE * 2 + NII * 2;
  for (int i = tid; i < total; i += gridDim.x * blockDim.x) {
    int x = i;
    if (x < TS) { d_cE[x] = 0; continue; } x -= TS;
    if (x < TS) { d_cI[x] = 0; continue; } x -= TS;
    if (x < NEE) { d_csEae[x] = 0.f; continue; } x -= NEE;
    if (x < NEE) { d_csIae[x] = 0.f; continue; } x -= NEE;
    if (x < NII) { d_csEai[x] = 0.f; continue; } x -= NII;
    d_csIai[x] = 0.f;
  }
  if (tid == 0) d_barcnt = 0u;
}

// ---------------- K1: build spike matrix S (bf16 0/1, padded) ----------------
__global__ void k_spk(const float* __restrict__ inp, const float* __restrict__ rand_p) {
  int idx = blockIdx.x * blockDim.x + threadIdx.x;   // over 1024*1024
  if (idx >= TSP * INPN) return;
  int t = idx >> 10, i = idx & 1023;
  float v = 0.f;
  if (t < TS) v = (rand_p[(size_t)t * INPN + i] <= inp[i] * 0.5f) ? 1.f : 0.f;
  d_S[idx] = __float2bfloat16(v);
}

// ---------------- K2: split input-weight rows into hi/lo bf16 ----------------
__global__ void k_wsplit(const float* __restrict__ w_ae, const float* __restrict__ w_ai) {
  int idx = blockIdx.x * blockDim.x + threadIdx.x;   // over 1024*8000
  if (idx >= INPN * NN) return;
  int k = idx / NN, j = idx - k * NN;
  float w = (j < NEE) ? w_ae[(size_t)k * NEE + j] : w_ai[(size_t)k * NII + (j - NEE)];
  __nv_bfloat16 hi = __float2bfloat16(w);
  float lo = w - __bfloat162float(hi);
  d_Whi[idx] = hi;
  d_Wlo[idx] = __float2bfloat16(lo);
}

// ---------------- K3: column sums of E-row / I-row blocks ----------------
// which=0 -> w_ae (csEae/csIae), which=1 -> w_ai (csEai/csIai). 200-row chunks, MLP 8.
__global__ void k_colsum(const float* __restrict__ W, int ncols, int which) {
  int j = blockIdx.x * blockDim.x + threadIdx.x;
  if (j >= ncols) return;
  int c = blockIdx.y;   // 0..39 : 32 chunks of 200 E rows, 8 chunks of 200 I rows
  int base = (c < 32) ? (INPN + c * 200) : (INPN + NEE + (c - 32) * 200);
  const float* p = W + (size_t)base * ncols + j;
  float s = 0.f;
#pragma unroll 8
  for (int r = 0; r < 200; ++r) s += p[(size_t)r * ncols];
  float* dst;
  if (c < 32) dst = which ? d_csEai : d_csEae;
  else        dst = which ? d_csIai : d_csIae;
  atomicAdd(&dst[j], s);
}

// ---------------- K4: tensor-core GEMM  D = S x (Whi + Wlo) ----------------
// CTA tile 64x64, K-step 64, 4 warps (2x2), each warp 32x32 (2x2 wmma frags).
__global__ void __launch_bounds__(128) k_gemm() {
  __shared__ __nv_bfloat16 sA [64][72];
  __shared__ __nv_bfloat16 sBh[64][72];
  __shared__ __nv_bfloat16 sBl[64][72];

  const int bn = blockIdx.x;            // 0..124
  const int bm = blockIdx.y;            // 0..15
  const int tid = threadIdx.x;
  const int warp = tid >> 5;
  const int wm = warp >> 1, wn = warp & 1;

  wmma::fragment<wmma::accumulator, 16, 16, 16, float> acc[2][2];
#pragma unroll
  for (int mm = 0; mm < 2; ++mm)
#pragma unroll
    for (int nn = 0; nn < 2; ++nn) wmma::fill_fragment(acc[mm][nn], 0.0f);

  for (int kt = 0; kt < 16; ++kt) {
    // stage A: 64x64 bf16 = 512 uint4
#pragma unroll
    for (int u = 0; u < 4; ++u) {
      int idx = tid + u * 128;
      int row = idx >> 3, c8 = idx & 7;
      *(uint4*)&sA[row][c8 * 8] =
          *(const uint4*)&d_S[(size_t)(bm * 64 + row) * INPN + kt * 64 + c8 * 8];
    }
    // stage Bhi/Blo
#pragma unroll
    for (int u = 0; u < 4; ++u) {
      int idx = tid + u * 128;
      int row = idx >> 3, c8 = idx & 7;
      size_t g = (size_t)(kt * 64 + row) * NN + bn * 64 + c8 * 8;
      *(uint4*)&sBh[row][c8 * 8] = *(const uint4*)&d_Whi[g];
      *(uint4*)&sBl[row][c8 * 8] = *(const uint4*)&d_Wlo[g];
    }
    __syncthreads();

#pragma unroll
    for (int kk = 0; kk < 4; ++kk) {
      wmma::fragment<wmma::matrix_a, 16, 16, 16, __nv_bfloat16, wmma::row_major> af[2];
      wmma::fragment<wmma::matrix_b, 16, 16, 16, __nv_bfloat16, wmma::row_major> bh[2], bl[2];
#pragma unroll
      for (int mm = 0; mm < 2; ++mm)
        wmma::load_matrix_sync(af[mm], &sA[wm * 32 + mm * 16][kk * 16], 72);
#pragma unroll
      for (int nn = 0; nn < 2; ++nn) {
        wmma::load_matrix_sync(bh[nn], &sBh[kk * 16][wn * 32 + nn * 16], 72);
        wmma::load_matrix_sync(bl[nn], &sBl[kk * 16][wn * 32 + nn * 16], 72);
      }
#pragma unroll
      for (int mm = 0; mm < 2; ++mm)
#pragma unroll
        for (int nn = 0; nn < 2; ++nn) {
          wmma::mma_sync(acc[mm][nn], af[mm], bh[nn], acc[mm][nn]);
          wmma::mma_sync(acc[mm][nn], af[mm], bl[nn], acc[mm][nn]);
        }
    }
    __syncthreads();
  }

#pragma unroll
  for (int mm = 0; mm < 2; ++mm)
#pragma unroll
    for (int nn = 0; nn < 2; ++nn) {
      int r0 = bm * 64 + wm * 32 + mm * 16;
      int c0 = bn * 64 + wn * 32 + nn * 16;
      wmma::store_matrix_sync(&d_Dp[(size_t)r0 * NN + c0], acc[mm][nn], NN,
                              wmma::mem_row_major);
    }
}

// ---------------- K5: persistent recurrent simulation ----------------
__device__ __forceinline__ float gather_group(const float* __restrict__ base, int stride,
                                              const unsigned* __restrict__ mask,
                                              int cnt, int gsize, int nw, float colsum) {
  if (cnt == 0)     return 0.f;
  if (cnt == gsize) return colsum;                 // full activity -> exact column sum
  bool comp = (2 * cnt > gsize);
  float acc = comp ? colsum : 0.f;
  float sgn = comp ? -1.f : 1.f;
  for (int wd = 0; wd < nw; ++wd) {
    unsigned x = __ldcg(&mask[wd]);
    if (comp) x = ~x;
    while (x) {                                    // warp-uniform, deterministic order
      int b = __ffs(x) - 1;
      x &= x - 1;
      acc = fmaf(sgn, __ldg(base + (size_t)(wd * 32 + b) * stride), acc);
    }
  }
  return acc;
}

__global__ void __launch_bounds__(SIM_NT, 1) k_sim(const float* __restrict__ w_ae,
                                                   const float* __restrict__ w_ai,
                                                   float* __restrict__ out) {
  __shared__ int s_pc[WPC];
  const int tid = blockIdx.x * SIM_NT + threadIdx.x;   // 25*320 = 8000: all active
  const bool isE = (tid < NEE);                        // uniform per CTA
  const int col = isE ? tid : tid - NEE;
  const int stride = isE ? NEE : NII;
  const float* W = isE ? w_ae : w_ai;
  const float* baseE = W + (size_t)INPN * stride + col;
  const float* baseI = W + (size_t)(INPN + NEE) * stride + col;
  const float csE = isE ? d_csEae[col] : d_csEai[col];
  const float csI = isE ? d_csIae[col] : d_csIai[col];
  float v = 0.f, ssum = 0.f;
  const unsigned nb = gridDim.x;

  for (int t = 0; t < TS; ++t) {
    float a = __ldg(&d_Dp[(size_t)t * NN + tid]);
    int ageE = t - (isE ? 2 : 1);
    int ageI = t - (isE ? 1 : 2);
    if (ageE >= 0) {
      int c = __ldcg(&d_cE[ageE]);
      a += gather_group(baseE, stride, d_mE[ageE % 3], c, NEE, NWE, csE);
    }
    if (ageI >= 0) {
      int c = __ldcg(&d_cI[ageI]);
      a += gather_group(baseI, stride, d_mI[ageI % 3], c, NII, NWI, csI);
    }
    v = v * DECAYF + a;
    bool sp = (v >= VTHF);
    if (sp) v = 0.f;
    if (sp && isE && t >= PRB0) ssum += 1.f;

    unsigned bal = __ballot_sync(0xffffffffu, sp);
    if ((threadIdx.x & 31) == 0) {
      int gw = tid >> 5;
      int s = t % 3;
      if (isE) d_mE[s][gw] = bal;
      else     d_mI[s][gw - NWE] = bal;
      s_pc[threadIdx.x >> 5] = __popc(bal);
    }
    __syncthreads();
    if (threadIdx.x == 0) {
      int tot = 0;
#pragma unroll
      for (int w = 0; w < WPC; ++w) tot += s_pc[w];
      if (isE) atomicAdd(&d_cE[t], tot);
      else     atomicAdd(&d_cI[t], tot);
      __threadfence();
      atomicAdd((unsigned*)&d_barcnt, 1u);
      unsigned want = (unsigned)(t + 1) * nb;
      while (d_barcnt < want) { }
      __threadfence();
    }
    __syncthreads();
  }
  if (isE) out[col] = ssum * (1.0f / 800.0f);
}

// ---------------- launcher ----------------
extern "C" void kernel_launch(void* const* d_in, const int* in_sizes, int n_in,
                              void* d_out, int out_size) {
  const float *inp = 0, *w_ae = 0, *w_ai = 0, *rand_p = 0;
  for (int i = 0; i < n_in; ++i) {
    switch (in_sizes[i]) {
      case 1024:      inp    = (const float*)d_in[i]; break;
      case 57753600:  w_ae   = (const float*)d_in[i]; break;   // 9024*6400
      case 14438400:  w_ai   = (const float*)d_in[i]; break;   // 9024*1600
      case 1024000:   rand_p = (const float*)d_in[i]; break;   // 1000*1024
    }
  }
  float* out = (float*)d_out;

  k_reset<<<32, 256>>>();
  k_spk<<<(TSP * INPN + 255) / 256, 256>>>(inp, rand_p);
  k_wsplit<<<(INPN * NN + 255) / 256, 256>>>(w_ae, w_ai);
  {
    dim3 g((NEE + 255) / 256, 40);
    k_colsum<<<g, 256>>>(w_ae, NEE, 0);
  }
  {
    dim3 g((NII + 255) / 256, 40);
    k_colsum<<<g, 256>>>(w_ai, NII, 1);
  }
  {
    dim3 g(NN / 64, TSP / 64);   // 125 x 16
    k_gemm<<<g, 128>>>();
  }
  k_sim<<<SIM_NB, SIM_NT>>>(w_ae, w_ai, out);
}